// round 11
// baseline (speedup 1.0000x reference)
#include <cuda_runtime.h>
#include <cstdint>

// KA_BSpline_Core: out[n] = b_out + sum_q a[q] * spline_q( sigmoid(2*scale*(emb[n]·W[q]+b_inner[q])) )
//
// R11 = R5 (best: 104.7us) + 5th CTA per SM.
//  - coeffs/b_inner/a/scale/b_out moved to __constant__ (smem/CTA 46.4->45.1KB
//    so 5 CTAs fit incl. per-CTA reservation; staged via async D2D memcpy).
//  - __launch_bounds__(128, 5): 20 warps/SM (was 16; RF was the cap at 128 regs).
// Mainloop unchanged: warp-private cp.async double buffer, XOR swizzle,
// packed fma.rn.f32x2 GEMV, de Boor spline epilogue.

#define QDIM   12
#define KDIM   256
#define NCTRL  25
#define BLOCK  128
#define TILE   256           // points per block (2 per thread)
#define KCH    16
#define NCHUNK (KDIM / KCH)  // 16
#define BUF_FLOATS (TILE * KCH)                  // 4096
#define SMEM_FLOATS (2*BUF_FLOATS + QDIM*KDIM)   // 11264 -> 45056 B
#define SMEM_BYTES  (SMEM_FLOATS * 4)

__constant__ float c_coeffs[QDIM * NCTRL];
__constant__ float c_binner[QDIM];
__constant__ float c_aout[QDIM];
__constant__ float c_misc[2];   // [0]=inner_scale, [1]=b_out

__device__ __forceinline__ unsigned long long fma2(unsigned long long a,
                                                   unsigned long long b,
                                                   unsigned long long c) {
    unsigned long long d;
    asm("fma.rn.f32x2 %0, %1, %2, %3;" : "=l"(d) : "l"(a), "l"(b), "l"(c));
    return d;
}

// knots: [0,0,0,0, 1/22 .. 21/22, 1,1,1,1]  -> knot(t) for t in [0,28]
__device__ __forceinline__ float knotv(int t) {
    t -= 3;
    t = t < 0 ? 0 : (t > 22 ? 22 : t);
    return (float)t * (1.0f / 22.0f);
}

__global__ __launch_bounds__(BLOCK, 5)
void kan_bspline_kernel(const float* __restrict__ emb,
                        const float* __restrict__ W,
                        float* __restrict__ out,
                        int npts) {
    extern __shared__ float sh[];
    float* bufs = sh;                          // 2 * BUF_FLOATS
    float* Wsh  = sh + 2 * BUF_FLOATS;         // QDIM*KDIM = 3072

    const int tid  = threadIdx.x;
    const int wid  = tid >> 5;                 // warp 0..3
    const int lane = tid & 31;
    const long long tile0 = (long long)blockIdx.x * TILE;
    const bool full_tile = (tile0 + TILE) <= (long long)npts;

    // ---- warp-private cp.async loader (identical to R5) ----
    // Warp w loads exactly the 64 rows its own lanes consume:
    //   rows w*32..w*32+31 (acc0) and +128 (acc1).
    // Lane l covers float4-slot (l&3) of rows (w*32 + (l>>2) + 8i), i=0..3.
    // XOR swizzle: slot = ccol ^ ((row>>1)&3) -> conflict-free fill & read.
    const int ccol  = lane & 3;
    const int rsub  = lane >> 2;               // 0..7
    const int rbase = wid * 32 + rsub;

    auto issue = [&](int kc, int b) {
        float* bb = bufs + b * BUF_FLOATS;
        const float* g0 = emb + kc * KCH + ccol * 4;
        if (full_tile) {
#pragma unroll
            for (int h = 0; h < 2; h++) {
#pragma unroll
                for (int i = 0; i < 4; i++) {
                    int row = h * 128 + rbase + 8 * i;
                    int slot = ccol ^ ((row >> 1) & 3);
                    unsigned sa = (unsigned)__cvta_generic_to_shared(bb + row * KCH + slot * 4);
                    asm volatile("cp.async.cg.shared.global [%0], [%1], 16;\n"
                                 :: "r"(sa), "l"(g0 + (tile0 + row) * KDIM));
                }
            }
        } else {
#pragma unroll
            for (int h = 0; h < 2; h++) {
#pragma unroll
                for (int i = 0; i < 4; i++) {
                    int row = h * 128 + rbase + 8 * i;
                    long long prow = tile0 + row;
                    int ok = (prow < (long long)npts);
                    const float* gp = ok ? (g0 + prow * KDIM) : emb;
                    int sz = ok ? 16 : 0;
                    int slot = ccol ^ ((row >> 1) & 3);
                    unsigned sa = (unsigned)__cvta_generic_to_shared(bb + row * KCH + slot * 4);
                    asm volatile("cp.async.cg.shared.global [%0], [%1], 16, %2;\n"
                                 :: "r"(sa), "l"(gp), "r"(sz));
                }
            }
        }
        asm volatile("cp.async.commit_group;\n" ::: "memory");
    };

    issue(0, 0);

    // ---- stage W into smem ----
    for (int i = tid; i < QDIM * KDIM / 4; i += BLOCK)
        ((float4*)Wsh)[i] = ((const float4*)W)[i];
    __syncthreads();   // the only block barrier

    unsigned long long acc0[QDIM], acc1[QDIM];
#pragma unroll
    for (int q = 0; q < QDIM; q++) { acc0[q] = 0ULL; acc1[q] = 0ULL; }

    const int sw = (tid >> 1) & 3;   // read-side swizzle (same for row tid and tid+128)

#pragma unroll 1
    for (int c = 0; c < NCHUNK; c++) {
        if (c + 1 < NCHUNK) {
            issue(c + 1, (c + 1) & 1);
            asm volatile("cp.async.wait_group 1;\n" ::: "memory");
        } else {
            asm volatile("cp.async.wait_group 0;\n" ::: "memory");
        }
        __syncwarp();

        const float* row0 = bufs + (c & 1) * BUF_FLOATS + tid * KCH;
        const float* row1 = row0 + BLOCK * KCH;         // point tid + 128
        const float* wb   = Wsh + c * KCH;
#pragma unroll
        for (int k4 = 0; k4 < KCH / 4; k4++) {
            const int slot = (k4 ^ sw) * 4;
            ulonglong2 x0 = *(const ulonglong2*)(row0 + slot);
            ulonglong2 x1 = *(const ulonglong2*)(row1 + slot);
#pragma unroll
            for (int q = 0; q < QDIM; q++) {
                ulonglong2 w = *(const ulonglong2*)(wb + q * KDIM + k4 * 4);
                acc0[q] = fma2(x0.x, w.x, acc0[q]);
                acc0[q] = fma2(x0.y, w.y, acc0[q]);
                acc1[q] = fma2(x1.x, w.x, acc1[q]);
                acc1[q] = fma2(x1.y, w.y, acc1[q]);
            }
        }
        __syncwarp();
    }

    // ---- epilogue: sigmoid + cubic B-spline (de Boor) for both points ----
    const float is = c_misc[0];
#pragma unroll
    for (int pp = 0; pp < 2; pp++) {
        long long myp = tile0 + tid + pp * BLOCK;
        if (myp >= (long long)npts) break;
        const unsigned long long* acc = pp ? acc1 : acc0;
        float res = c_misc[1];
#pragma unroll
        for (int q = 0; q < QDIM; q++) {
            float lo, hi;
            asm("mov.b64 {%0, %1}, %2;" : "=f"(lo), "=f"(hi) : "l"(acc[q]));
            float u = lo + hi + c_binner[q];
            // s = 0.5*(tanh(is*u)+1) = 1/(1+exp(-2*is*u))
            float e = __expf(-2.0f * is * u);
            float s = __fdividef(1.0f, 1.0f + e);

            int j = (int)(s * 22.0f);
            j = j < 0 ? 0 : (j > 21 ? 21 : j);
            const int i = j + 3;   // knot span: knots[i] <= s < knots[i+1]

            float Nb[4], lft[4], rgt[4];
            Nb[0] = 1.0f;
#pragma unroll
            for (int p = 1; p <= 3; p++) {
                lft[p] = s - knotv(i + 1 - p);
                rgt[p] = knotv(i + p) - s;
                float saved = 0.0f;
#pragma unroll
                for (int r = 0; r < p; r++) {
                    float den = rgt[r + 1] + lft[p - r];
                    float tmp = __fdividef(Nb[r], den);
                    Nb[r] = fmaf(rgt[r + 1], tmp, saved);
                    saved = lft[p - r] * tmp;
                }
                Nb[p] = saved;
            }
            const float* cq = c_coeffs + q * NCTRL + j;   // coeff index (i-3)..i
            float phi = Nb[0] * cq[0] + Nb[1] * cq[1] + Nb[2] * cq[2] + Nb[3] * cq[3];
            res = fmaf(c_aout[q], phi, res);
        }
        out[myp] = res;
    }
}

extern "C" void kernel_launch(void* const* d_in, const int* in_sizes, int n_in,
                              void* d_out, int out_size) {
    const float* emb         = (const float*)d_in[0];
    const float* W           = (const float*)d_in[1];
    const float* b_inner     = (const float*)d_in[2];
    const float* inner_scale = (const float*)d_in[3];
    const float* coeffs      = (const float*)d_in[4];
    const float* a           = (const float*)d_in[5];
    const float* b_out       = (const float*)d_in[6];
    float* out = (float*)d_out;

    // Stage small params into __constant__ (async D2D copies: graph-capturable).
    cudaMemcpyToSymbolAsync(c_coeffs, coeffs, QDIM * NCTRL * sizeof(float), 0,
                            cudaMemcpyDeviceToDevice);
    cudaMemcpyToSymbolAsync(c_binner, b_inner, QDIM * sizeof(float), 0,
                            cudaMemcpyDeviceToDevice);
    cudaMemcpyToSymbolAsync(c_aout, a, QDIM * sizeof(float), 0,
                            cudaMemcpyDeviceToDevice);
    cudaMemcpyToSymbolAsync(c_misc, inner_scale, sizeof(float), 0,
                            cudaMemcpyDeviceToDevice);
    cudaMemcpyToSymbolAsync(c_misc, b_out, sizeof(float), sizeof(float),
                            cudaMemcpyDeviceToDevice);

    int npts = out_size;   // (N_POINTS, 1) float32
    int blocks = (npts + TILE - 1) / TILE;

    cudaFuncSetAttribute(kan_bspline_kernel,
                         cudaFuncAttributeMaxDynamicSharedMemorySize, SMEM_BYTES);
    kan_bspline_kernel<<<blocks, BLOCK, SMEM_BYTES>>>(emb, W, out, npts);
}

// round 12
// speedup vs baseline: 1.2265x; 1.2265x over previous
#include <cuda_runtime.h>
#include <cstdint>

// KA_BSpline_Core: out[n] = b_out + sum_q a[q] * spline_q( sigmoid(2*scale*(emb[n]·W[q]+b_inner[q])) )
//
// R12 = R5 (best: 104.7us) with W moved from smem to __constant__.
// The 768 W LDS.128 per thread were warp-uniform re-reads (12KB of W
// re-fetched per point pair): through the constant/uniform datapath they
// leave the LSU crossbar and most of the issue budget. One D2D memcpy
// graph node stages W. Everything else identical to R5.

#define QDIM   12
#define KDIM   256
#define NCTRL  25
#define BLOCK  128
#define TILE   256           // points per block (2 per thread)
#define KCH    16
#define NCHUNK (KDIM / KCH)  // 16
#define BUF_FLOATS (TILE * KCH)                  // 4096
#define SMEM_FLOATS (2*BUF_FLOATS + QDIM*NCTRL + 32)
#define SMEM_BYTES  (SMEM_FLOATS * 4)

__constant__ float c_W[QDIM * KDIM];   // 12KB

__device__ __forceinline__ unsigned long long fma2(unsigned long long a,
                                                   unsigned long long b,
                                                   unsigned long long c) {
    unsigned long long d;
    asm("fma.rn.f32x2 %0, %1, %2, %3;" : "=l"(d) : "l"(a), "l"(b), "l"(c));
    return d;
}

// knots: [0,0,0,0, 1/22 .. 21/22, 1,1,1,1]  -> knot(t) for t in [0,28]
__device__ __forceinline__ float knotv(int t) {
    t -= 3;
    t = t < 0 ? 0 : (t > 22 ? 22 : t);
    return (float)t * (1.0f / 22.0f);
}

__global__ __launch_bounds__(BLOCK, 4)
void kan_bspline_kernel(const float* __restrict__ emb,
                        const float* __restrict__ b_inner,
                        const float* __restrict__ inner_scale,
                        const float* __restrict__ coeffs,
                        const float* __restrict__ a_out,
                        const float* __restrict__ b_out,
                        float* __restrict__ out,
                        int npts) {
    extern __shared__ float sh[];
    float* bufs = sh;                          // 2 * BUF_FLOATS
    float* Csh  = sh + 2 * BUF_FLOATS;         // QDIM*NCTRL = 300
    float* Msh  = Csh + QDIM * NCTRL;          // [0..11]=b_inner [12..23]=a [24]=scale [25]=b_out

    const int tid  = threadIdx.x;
    const int wid  = tid >> 5;                 // warp 0..3
    const int lane = tid & 31;
    const long long tile0 = (long long)blockIdx.x * TILE;
    const bool full_tile = (tile0 + TILE) <= (long long)npts;

    // ---- warp-private cp.async loader (identical to R5) ----
    // Warp w loads exactly the 64 rows its own lanes consume:
    //   rows w*32..w*32+31 (acc0) and +128 (acc1).
    // Lane l covers float4-slot (l&3) of rows (w*32 + (l>>2) + 8i), i=0..3.
    // XOR swizzle: slot = ccol ^ ((row>>1)&3) -> conflict-free fill & read.
    const int ccol  = lane & 3;
    const int rsub  = lane >> 2;               // 0..7
    const int rbase = wid * 32 + rsub;

    auto issue = [&](int kc, int b) {
        float* bb = bufs + b * BUF_FLOATS;
        const float* g0 = emb + kc * KCH + ccol * 4;
        if (full_tile) {
#pragma unroll
            for (int h = 0; h < 2; h++) {
#pragma unroll
                for (int i = 0; i < 4; i++) {
                    int row = h * 128 + rbase + 8 * i;
                    int slot = ccol ^ ((row >> 1) & 3);
                    unsigned sa = (unsigned)__cvta_generic_to_shared(bb + row * KCH + slot * 4);
                    asm volatile("cp.async.cg.shared.global [%0], [%1], 16;\n"
                                 :: "r"(sa), "l"(g0 + (tile0 + row) * KDIM));
                }
            }
        } else {
#pragma unroll
            for (int h = 0; h < 2; h++) {
#pragma unroll
                for (int i = 0; i < 4; i++) {
                    int row = h * 128 + rbase + 8 * i;
                    long long prow = tile0 + row;
                    int ok = (prow < (long long)npts);
                    const float* gp = ok ? (g0 + prow * KDIM) : emb;
                    int sz = ok ? 16 : 0;
                    int slot = ccol ^ ((row >> 1) & 3);
                    unsigned sa = (unsigned)__cvta_generic_to_shared(bb + row * KCH + slot * 4);
                    asm volatile("cp.async.cg.shared.global [%0], [%1], 16, %2;\n"
                                 :: "r"(sa), "l"(gp), "r"(sz));
                }
            }
        }
        asm volatile("cp.async.commit_group;\n" ::: "memory");
    };

    issue(0, 0);

    // ---- stage small params into smem ----
    for (int i = tid; i < QDIM * NCTRL; i += BLOCK)
        Csh[i] = coeffs[i];
    if (tid < QDIM) { Msh[tid] = b_inner[tid]; Msh[12 + tid] = a_out[tid]; }
    if (tid == 0)   { Msh[24] = inner_scale[0]; Msh[25] = b_out[0]; }
    __syncthreads();   // the only block barrier

    unsigned long long acc0[QDIM], acc1[QDIM];
#pragma unroll
    for (int q = 0; q < QDIM; q++) { acc0[q] = 0ULL; acc1[q] = 0ULL; }

    const int sw = (tid >> 1) & 3;   // read-side swizzle (same for row tid and tid+128)

#pragma unroll 1
    for (int c = 0; c < NCHUNK; c++) {
        if (c + 1 < NCHUNK) {
            issue(c + 1, (c + 1) & 1);
            asm volatile("cp.async.wait_group 1;\n" ::: "memory");
        } else {
            asm volatile("cp.async.wait_group 0;\n" ::: "memory");
        }
        __syncwarp();

        const float* row0 = bufs + (c & 1) * BUF_FLOATS + tid * KCH;
        const float* row1 = row0 + BLOCK * KCH;         // point tid + 128
        const float* wb   = c_W + c * KCH;              // constant-memory W (uniform)
#pragma unroll
        for (int k4 = 0; k4 < KCH / 4; k4++) {
            const int slot = (k4 ^ sw) * 4;
            ulonglong2 x0 = *(const ulonglong2*)(row0 + slot);
            ulonglong2 x1 = *(const ulonglong2*)(row1 + slot);
#pragma unroll
            for (int q = 0; q < QDIM; q++) {
                ulonglong2 w = *(const ulonglong2*)(wb + q * KDIM + k4 * 4);
                acc0[q] = fma2(x0.x, w.x, acc0[q]);
                acc0[q] = fma2(x0.y, w.y, acc0[q]);
                acc1[q] = fma2(x1.x, w.x, acc1[q]);
                acc1[q] = fma2(x1.y, w.y, acc1[q]);
            }
        }
        __syncwarp();
    }

    // ---- epilogue: sigmoid + cubic B-spline (de Boor) for both points ----
    const float is = Msh[24];
#pragma unroll
    for (int pp = 0; pp < 2; pp++) {
        long long myp = tile0 + tid + pp * BLOCK;
        if (myp >= (long long)npts) break;
        const unsigned long long* acc = pp ? acc1 : acc0;
        float res = Msh[25];
#pragma unroll
        for (int q = 0; q < QDIM; q++) {
            float lo, hi;
            asm("mov.b64 {%0, %1}, %2;" : "=f"(lo), "=f"(hi) : "l"(acc[q]));
            float u = lo + hi + Msh[q];
            // s = 0.5*(tanh(is*u)+1) = 1/(1+exp(-2*is*u))
            float e = __expf(-2.0f * is * u);
            float s = __fdividef(1.0f, 1.0f + e);

            int j = (int)(s * 22.0f);
            j = j < 0 ? 0 : (j > 21 ? 21 : j);
            const int i = j + 3;   // knot span: knots[i] <= s < knots[i+1]

            float Nb[4], lft[4], rgt[4];
            Nb[0] = 1.0f;
#pragma unroll
            for (int p = 1; p <= 3; p++) {
                lft[p] = s - knotv(i + 1 - p);
                rgt[p] = knotv(i + p) - s;
                float saved = 0.0f;
#pragma unroll
                for (int r = 0; r < p; r++) {
                    float den = rgt[r + 1] + lft[p - r];
                    float tmp = __fdividef(Nb[r], den);
                    Nb[r] = fmaf(rgt[r + 1], tmp, saved);
                    saved = lft[p - r] * tmp;
                }
                Nb[p] = saved;
            }
            const float* cq = Csh + q * NCTRL + j;   // coeff index (i-3)..i
            float phi = Nb[0] * cq[0] + Nb[1] * cq[1] + Nb[2] * cq[2] + Nb[3] * cq[3];
            res = fmaf(Msh[12 + q], phi, res);
        }
        out[myp] = res;
    }
}

extern "C" void kernel_launch(void* const* d_in, const int* in_sizes, int n_in,
                              void* d_out, int out_size) {
    const float* emb         = (const float*)d_in[0];
    const float* W           = (const float*)d_in[1];
    const float* b_inner     = (const float*)d_in[2];
    const float* inner_scale = (const float*)d_in[3];
    const float* coeffs      = (const float*)d_in[4];
    const float* a           = (const float*)d_in[5];
    const float* b_out       = (const float*)d_in[6];
    float* out = (float*)d_out;

    // Single D2D memcpy node: stage W into __constant__.
    cudaMemcpyToSymbolAsync(c_W, W, QDIM * KDIM * sizeof(float), 0,
                            cudaMemcpyDeviceToDevice);

    int npts = out_size;   // (N_POINTS, 1) float32
    int blocks = (npts + TILE - 1) / TILE;

    cudaFuncSetAttribute(kan_bspline_kernel,
                         cudaFuncAttributeMaxDynamicSharedMemorySize, SMEM_BYTES);
    kan_bspline_kernel<<<blocks, BLOCK, SMEM_BYTES>>>(
        emb, b_inner, inner_scale, coeffs, a, b_out, out, npts);
}

// round 14
// speedup vs baseline: 1.2340x; 1.0061x over previous
#include <cuda_runtime.h>
#include <cstdint>

// KA_BSpline_Core: out[n] = b_out + sum_q a[q] * spline_q( sigmoid(2*scale*(emb[n]·W[q]+b_inner[q])) )
//
// R13 = R5 mainloop (best kernel: 104.4us) restructured as warp-autonomous
// persistent pipelines with atomic work stealing:
//  - each WARP is an independent pipeline on 64-point units (the R5 loader was
//    already warp-private: a warp loads exactly what its own lanes consume)
//  - unit ids come from a global atomic counter -> perfect load balance
//    (R6's static 4-vs-3-tile split caused a 21% spread and regressed)
//  - next unit's chunk 0 is issued at the current unit's last chunk: the
//    cp.async ring NEVER drains until the pool is empty
//  - counter reset each launch via a cudaMemsetAsync graph node.
// Per-chunk compute identical to R5: XOR-swizzled smem, packed fma.rn.f32x2.

#define QDIM   12
#define KDIM   256
#define NCTRL  25
#define BLOCK  128
#define UNIT   64            // points per warp work-unit (2 per lane)
#define KCH    16
#define NCHUNK (KDIM / KCH)  // 16
#define WBUF   (UNIT * KCH)  // 1024 floats per buffer per warp
#define BUFS_FLOATS (4 * 2 * WBUF)               // 4 warps x 2 buffers = 8192
#define SMEM_FLOATS (BUFS_FLOATS + QDIM*KDIM + QDIM*NCTRL + 32)
#define SMEM_BYTES  (SMEM_FLOATS * 4)
#define GRIDMAX 592          // 4 CTAs/SM x 148 SMs

__device__ int g_ctr;

__device__ __forceinline__ unsigned long long fma2(unsigned long long a,
                                                   unsigned long long b,
                                                   unsigned long long c) {
    unsigned long long d;
    asm("fma.rn.f32x2 %0, %1, %2, %3;" : "=l"(d) : "l"(a), "l"(b), "l"(c));
    return d;
}

// knots: [0,0,0,0, 1/22 .. 21/22, 1,1,1,1]  -> knot(t) for t in [0,28]
__device__ __forceinline__ float knotv(int t) {
    t -= 3;
    t = t < 0 ? 0 : (t > 22 ? 22 : t);
    return (float)t * (1.0f / 22.0f);
}

__global__ __launch_bounds__(BLOCK, 4)
void kan_bspline_kernel(const float* __restrict__ emb,
                        const float* __restrict__ W,
                        const float* __restrict__ b_inner,
                        const float* __restrict__ inner_scale,
                        const float* __restrict__ coeffs,
                        const float* __restrict__ a_out,
                        const float* __restrict__ b_out,
                        float* __restrict__ out,
                        int npts, int nunits, int nwarps) {
    extern __shared__ float sh[];
    float* bufs = sh;                          // BUFS_FLOATS
    float* Wsh  = sh + BUFS_FLOATS;            // QDIM*KDIM = 3072
    float* Csh  = Wsh + QDIM * KDIM;           // QDIM*NCTRL = 300
    float* Msh  = Csh + QDIM * NCTRL;          // [0..11]=b_inner [12..23]=a [24]=scale [25]=b_out

    const int tid  = threadIdx.x;
    const int wid  = tid >> 5;                 // warp 0..3
    const int lane = tid & 31;
    float* wbuf = bufs + wid * 2 * WBUF;       // this warp's private double buffer

    // ---- warp-private cp.async loader (R5 pattern on a 64-row unit) ----
    // Lane l covers float4-slot (l&3) of rows (l>>2) + 8i, i=0..7.
    // XOR swizzle: slot = ccol ^ ((row>>1)&3) -> conflict-free fill & read.
    const int ccol = lane & 3;
    const int rsub = lane >> 2;                // 0..7

    auto issue = [&](int unit, int kc, int b) {
        float* bb = wbuf + b * WBUF;
        const long long pbase = (long long)unit * UNIT;
        const float* g0 = emb + kc * KCH + ccol * 4;
        if (pbase + UNIT <= (long long)npts) {
#pragma unroll
            for (int i = 0; i < 8; i++) {
                int r = rsub + 8 * i;
                int slot = ccol ^ ((r >> 1) & 3);
                unsigned sa = (unsigned)__cvta_generic_to_shared(bb + r * KCH + slot * 4);
                asm volatile("cp.async.cg.shared.global [%0], [%1], 16;\n"
                             :: "r"(sa), "l"(g0 + (pbase + r) * KDIM));
            }
        } else {
#pragma unroll
            for (int i = 0; i < 8; i++) {
                int r = rsub + 8 * i;
                long long prow = pbase + r;
                int ok = (prow < (long long)npts);
                const float* gp = ok ? (g0 + prow * KDIM) : emb;
                int sz = ok ? 16 : 0;
                int slot = ccol ^ ((r >> 1) & 3);
                unsigned sa = (unsigned)__cvta_generic_to_shared(bb + r * KCH + slot * 4);
                asm volatile("cp.async.cg.shared.global [%0], [%1], 16, %2;\n"
                             :: "r"(sa), "l"(gp), "r"(sz));
            }
        }
        asm volatile("cp.async.commit_group;\n" ::: "memory");
    };

    int unit = blockIdx.x * 4 + wid;           // first unit: static (no atomic)
    if (unit < nunits) issue(unit, 0, 0);

    // ---- stage constants into smem ----
    for (int i = tid; i < QDIM * KDIM / 4; i += BLOCK)
        ((float4*)Wsh)[i] = ((const float4*)W)[i];
    for (int i = tid; i < QDIM * NCTRL; i += BLOCK)
        Csh[i] = coeffs[i];
    if (tid < QDIM) { Msh[tid] = b_inner[tid]; Msh[12 + tid] = a_out[tid]; }
    if (tid == 0)   { Msh[24] = inner_scale[0]; Msh[25] = b_out[0]; }
    __syncthreads();   // the only block barrier; warps free-run after this

    const int sw = (lane >> 1) & 3;   // read-side swizzle (rows lane and 32+lane agree)
    const float is = Msh[24];
    int gchunk = 0;                   // continuous chunk counter -> buffer parity

#pragma unroll 1
    while (unit < nunits) {
        // Steal the next unit now; latency hidden behind 16 chunks of work.
        int nxt_l0 = 0x7fffffff;
        if (lane == 0) nxt_l0 = nwarps + atomicAdd(&g_ctr, 1);
        int nxt = 0x7fffffff;

        unsigned long long acc0[QDIM], acc1[QDIM];
#pragma unroll
        for (int q = 0; q < QDIM; q++) { acc0[q] = 0ULL; acc1[q] = 0ULL; }

#pragma unroll 1
        for (int c = 0; c < NCHUNK; c++) {
            if (c + 1 < NCHUNK) {
                issue(unit, c + 1, (gchunk + 1) & 1);
                asm volatile("cp.async.wait_group 1;\n" ::: "memory");
            } else {
                nxt = __shfl_sync(0xffffffffu, nxt_l0, 0);
                if (nxt < nunits) {
                    issue(nxt, 0, (gchunk + 1) & 1);
                    asm volatile("cp.async.wait_group 1;\n" ::: "memory");
                } else {
                    asm volatile("cp.async.wait_group 0;\n" ::: "memory");
                }
            }
            __syncwarp();

            const float* r0 = wbuf + (gchunk & 1) * WBUF + lane * KCH;
            const float* r1 = r0 + 32 * KCH;            // row 32+lane
            const float* wb = Wsh + c * KCH;
#pragma unroll
            for (int k4 = 0; k4 < KCH / 4; k4++) {
                const int slot = (k4 ^ sw) * 4;
                ulonglong2 x0 = *(const ulonglong2*)(r0 + slot);
                ulonglong2 x1 = *(const ulonglong2*)(r1 + slot);
#pragma unroll
                for (int q = 0; q < QDIM; q++) {
                    ulonglong2 w = *(const ulonglong2*)(wb + q * KDIM + k4 * 4);
                    acc0[q] = fma2(x0.x, w.x, acc0[q]);
                    acc0[q] = fma2(x0.y, w.y, acc0[q]);
                    acc1[q] = fma2(x1.x, w.x, acc1[q]);
                    acc1[q] = fma2(x1.y, w.y, acc1[q]);
                }
            }
            __syncwarp();
            gchunk++;
        }

        // ---- epilogue: sigmoid + cubic B-spline (de Boor) for both points ----
        // (next unit's chunk 0 is streaming via cp.async while this runs)
        const long long pbase = (long long)unit * UNIT;
#pragma unroll
        for (int pp = 0; pp < 2; pp++) {
            long long myp = pbase + lane + pp * 32;
            if (myp < (long long)npts) {
                const unsigned long long* acc = pp ? acc1 : acc0;
                float res = Msh[25];
#pragma unroll
                for (int q = 0; q < QDIM; q++) {
                    float lo, hi;
                    asm("mov.b64 {%0, %1}, %2;" : "=f"(lo), "=f"(hi) : "l"(acc[q]));
                    float u = lo + hi + Msh[q];
                    // s = 0.5*(tanh(is*u)+1) = 1/(1+exp(-2*is*u))
                    float e = __expf(-2.0f * is * u);
                    float s = __fdividef(1.0f, 1.0f + e);

                    int j = (int)(s * 22.0f);
                    j = j < 0 ? 0 : (j > 21 ? 21 : j);
                    const int i = j + 3;   // knot span: knots[i] <= s < knots[i+1]

                    float Nb[4], lft[4], rgt[4];
                    Nb[0] = 1.0f;
#pragma unroll
                    for (int p = 1; p <= 3; p++) {
                        lft[p] = s - knotv(i + 1 - p);
                        rgt[p] = knotv(i + p) - s;
                        float saved = 0.0f;
#pragma unroll
                        for (int r = 0; r < p; r++) {
                            float den = rgt[r + 1] + lft[p - r];
                            float tmp = __fdividef(Nb[r], den);
                            Nb[r] = fmaf(rgt[r + 1], tmp, saved);
                            saved = lft[p - r] * tmp;
                        }
                        Nb[p] = saved;
                    }
                    const float* cq = Csh + q * NCTRL + j;   // coeff index (i-3)..i
                    float phi = Nb[0] * cq[0] + Nb[1] * cq[1] + Nb[2] * cq[2] + Nb[3] * cq[3];
                    res = fmaf(Msh[12 + q], phi, res);
                }
                out[myp] = res;
            }
        }
        unit = nxt;
    }
}

extern "C" void kernel_launch(void* const* d_in, const int* in_sizes, int n_in,
                              void* d_out, int out_size) {
    const float* emb         = (const float*)d_in[0];
    const float* W           = (const float*)d_in[1];
    const float* b_inner     = (const float*)d_in[2];
    const float* inner_scale = (const float*)d_in[3];
    const float* coeffs      = (const float*)d_in[4];
    const float* a           = (const float*)d_in[5];
    const float* b_out       = (const float*)d_in[6];
    float* out = (float*)d_out;

    int npts   = out_size;                    // (N_POINTS, 1) float32
    int nunits = (npts + UNIT - 1) / UNIT;
    int blocks = (nunits + 3) / 4;
    if (blocks > GRIDMAX) blocks = GRIDMAX;
    int nwarps = blocks * 4;

    // Reset the work-stealing counter (memset node: graph-capturable).
    void* ctr_ptr = nullptr;
    cudaGetSymbolAddress(&ctr_ptr, g_ctr);
    cudaMemsetAsync(ctr_ptr, 0, sizeof(int));

    cudaFuncSetAttribute(kan_bspline_kernel,
                         cudaFuncAttributeMaxDynamicSharedMemorySize, SMEM_BYTES);
    kan_bspline_kernel<<<blocks, BLOCK, SMEM_BYTES>>>(
        emb, W, b_inner, inner_scale, coeffs, a, b_out, out,
        npts, nunits, nwarps);
}

// round 16
// speedup vs baseline: 1.2557x; 1.0176x over previous
#include <cuda_runtime.h>
#include <cstdint>

// KA_BSpline_Core: out[n] = b_out + sum_q a[q] * spline_q( sigmoid(2*scale*(emb[n]·W[q]+b_inner[q])) )
//
// R15 = R5 mainloop (best: 104.7us) UNCHANGED + two scheduling fixes:
//  - 592 persistent CTAs pulling 256-pt tiles from an atomic counter
//    (CTA-granular stealing: <=1-tile imbalance; R6's static stride lost 21%)
//  - cross-tile chunk-0 prefetch at chunk 15 (ring never drains; epilogue
//    overlaps the next tile's DRAM stream)
// One __syncthreads per tile (mid-tile) publishes the stolen tile id.

#define QDIM   12
#define KDIM   256
#define NCTRL  25
#define BLOCK  128
#define TILE   256           // points per tile (2 per thread)
#define KCH    16
#define NCHUNK (KDIM / KCH)  // 16
#define BUF_FLOATS (TILE * KCH)                  // 4096
#define SMEM_FLOATS (2*BUF_FLOATS + QDIM*KDIM + QDIM*NCTRL + 32)
#define SMEM_BYTES  (SMEM_FLOATS * 4)
#define GRIDMAX 592          // 4 CTAs/SM x 148 SMs

__device__ int g_ctr;

__device__ __forceinline__ unsigned long long fma2(unsigned long long a,
                                                   unsigned long long b,
                                                   unsigned long long c) {
    unsigned long long d;
    asm("fma.rn.f32x2 %0, %1, %2, %3;" : "=l"(d) : "l"(a), "l"(b), "l"(c));
    return d;
}

// knots: [0,0,0,0, 1/22 .. 21/22, 1,1,1,1]  -> knot(t) for t in [0,28]
__device__ __forceinline__ float knotv(int t) {
    t -= 3;
    t = t < 0 ? 0 : (t > 22 ? 22 : t);
    return (float)t * (1.0f / 22.0f);
}

__global__ __launch_bounds__(BLOCK, 4)
void kan_bspline_kernel(const float* __restrict__ emb,
                        const float* __restrict__ W,
                        const float* __restrict__ b_inner,
                        const float* __restrict__ inner_scale,
                        const float* __restrict__ coeffs,
                        const float* __restrict__ a_out,
                        const float* __restrict__ b_out,
                        float* __restrict__ out,
                        int npts, int ntiles, int nctas) {
    extern __shared__ float sh[];
    float* bufs = sh;                          // 2 * BUF_FLOATS
    float* Wsh  = sh + 2 * BUF_FLOATS;         // QDIM*KDIM = 3072
    float* Csh  = Wsh + QDIM * KDIM;           // QDIM*NCTRL = 300
    float* Msh  = Csh + QDIM * NCTRL;          // [0..11]=b_inner [12..23]=a [24]=scale [25]=b_out
    int*   Nxt  = (int*)(Msh + 26);            // [0..1]: stolen tile id, by tile parity

    const int tid  = threadIdx.x;
    const int wid  = tid >> 5;                 // warp 0..3
    const int lane = tid & 31;

    // ---- warp-private cp.async loader (identical to R5) ----
    // Warp w loads exactly the 64 rows its own lanes consume:
    //   rows w*32..w*32+31 (acc0) and +128 (acc1).
    // Lane l covers float4-slot (l&3) of rows (w*32 + (l>>2) + 8i), i=0..3.
    // XOR swizzle: slot = ccol ^ ((row>>1)&3) -> conflict-free fill & read.
    const int ccol  = lane & 3;
    const int rsub  = lane >> 2;               // 0..7
    const int rbase = wid * 32 + rsub;

    auto issue = [&](int tile, int kc, int b) {
        float* bb = bufs + b * BUF_FLOATS;
        const long long tile0 = (long long)tile * TILE;
        const float* g0 = emb + kc * KCH + ccol * 4;
        if (tile0 + TILE <= (long long)npts) {
#pragma unroll
            for (int h = 0; h < 2; h++) {
#pragma unroll
                for (int i = 0; i < 4; i++) {
                    int row = h * 128 + rbase + 8 * i;
                    int slot = ccol ^ ((row >> 1) & 3);
                    unsigned sa = (unsigned)__cvta_generic_to_shared(bb + row * KCH + slot * 4);
                    asm volatile("cp.async.cg.shared.global [%0], [%1], 16;\n"
                                 :: "r"(sa), "l"(g0 + (tile0 + row) * KDIM));
                }
            }
        } else {
#pragma unroll
            for (int h = 0; h < 2; h++) {
#pragma unroll
                for (int i = 0; i < 4; i++) {
                    int row = h * 128 + rbase + 8 * i;
                    long long prow = tile0 + row;
                    int ok = (prow < (long long)npts);
                    const float* gp = ok ? (g0 + prow * KDIM) : emb;
                    int sz = ok ? 16 : 0;
                    int slot = ccol ^ ((row >> 1) & 3);
                    unsigned sa = (unsigned)__cvta_generic_to_shared(bb + row * KCH + slot * 4);
                    asm volatile("cp.async.cg.shared.global [%0], [%1], 16, %2;\n"
                                 :: "r"(sa), "l"(gp), "r"(sz));
                }
            }
        }
        asm volatile("cp.async.commit_group;\n" ::: "memory");
    };

    int tile = blockIdx.x;                     // first tile: static
    if (tile < ntiles) issue(tile, 0, 0);

    // ---- stage constants into smem ----
    for (int i = tid; i < QDIM * KDIM / 4; i += BLOCK)
        ((float4*)Wsh)[i] = ((const float4*)W)[i];
    for (int i = tid; i < QDIM * NCTRL; i += BLOCK)
        Csh[i] = coeffs[i];
    if (tid < QDIM) { Msh[tid] = b_inner[tid]; Msh[12 + tid] = a_out[tid]; }
    if (tid == 0)   { Msh[24] = inner_scale[0]; Msh[25] = b_out[0]; }
    __syncthreads();

    const int sw = (tid >> 1) & 3;   // read-side swizzle (same for row tid and tid+128)
    const float is = Msh[24];
    int gchunk = 0;                  // continuous chunk counter -> buffer parity
    int tpar = 0;                    // tile parity for the Nxt slot

#pragma unroll 1
    while (tile < ntiles) {
        const long long tile0 = (long long)tile * TILE;

        // Steal the next tile now (warp 0); consumed at chunk 15 after the
        // mid-tile barrier. Latency fully hidden behind ~8 chunks of work.
        if (wid == 0 && lane == 0)
            Nxt[tpar] = nctas + atomicAdd(&g_ctr, 1);

        unsigned long long acc0[QDIM], acc1[QDIM];
#pragma unroll
        for (int q = 0; q < QDIM; q++) { acc0[q] = 0ULL; acc1[q] = 0ULL; }

        int nxt = 0;
#pragma unroll 1
        for (int c = 0; c < NCHUNK; c++) {
            if (c + 1 < NCHUNK) {
                issue(tile, c + 1, (gchunk + 1) & 1);
                asm volatile("cp.async.wait_group 1;\n" ::: "memory");
            } else {
                if (nxt < ntiles) {
                    issue(nxt, 0, (gchunk + 1) & 1);
                    asm volatile("cp.async.wait_group 1;\n" ::: "memory");
                } else {
                    asm volatile("cp.async.wait_group 0;\n" ::: "memory");
                }
            }
            __syncwarp();

            const float* row0 = bufs + (gchunk & 1) * BUF_FLOATS + tid * KCH;
            const float* row1 = row0 + BLOCK * KCH;     // point tid + 128
            const float* wb   = Wsh + c * KCH;
#pragma unroll
            for (int k4 = 0; k4 < KCH / 4; k4++) {
                const int slot = (k4 ^ sw) * 4;
                ulonglong2 x0 = *(const ulonglong2*)(row0 + slot);
                ulonglong2 x1 = *(const ulonglong2*)(row1 + slot);
#pragma unroll
                for (int q = 0; q < QDIM; q++) {
                    ulonglong2 w = *(const ulonglong2*)(wb + q * KDIM + k4 * 4);
                    acc0[q] = fma2(x0.x, w.x, acc0[q]);
                    acc0[q] = fma2(x0.y, w.y, acc0[q]);
                    acc1[q] = fma2(x1.x, w.x, acc1[q]);
                    acc1[q] = fma2(x1.y, w.y, acc1[q]);
                }
            }
            __syncwarp();
            gchunk++;

            if (c == 7) {
                __syncthreads();          // publish Nxt[tpar] to all warps
                nxt = Nxt[tpar];
            }
        }

        // ---- epilogue: sigmoid + cubic B-spline (de Boor) for both points ----
        // (next tile's chunk 0 is streaming via cp.async while this runs)
#pragma unroll
        for (int pp = 0; pp < 2; pp++) {
            long long myp = tile0 + tid + pp * BLOCK;
            if (myp < (long long)npts) {
                const unsigned long long* acc = pp ? acc1 : acc0;
                float res = Msh[25];
#pragma unroll
                for (int q = 0; q < QDIM; q++) {
                    float lo, hi;
                    asm("mov.b64 {%0, %1}, %2;" : "=f"(lo), "=f"(hi) : "l"(acc[q]));
                    float u = lo + hi + Msh[q];
                    // s = 0.5*(tanh(is*u)+1) = 1/(1+exp(-2*is*u))
                    float e = __expf(-2.0f * is * u);
                    float s = __fdividef(1.0f, 1.0f + e);

                    int j = (int)(s * 22.0f);
                    j = j < 0 ? 0 : (j > 21 ? 21 : j);
                    const int i = j + 3;   // knot span: knots[i] <= s < knots[i+1]

                    float Nb[4], lft[4], rgt[4];
                    Nb[0] = 1.0f;
#pragma unroll
                    for (int p = 1; p <= 3; p++) {
                        lft[p] = s - knotv(i + 1 - p);
                        rgt[p] = knotv(i + p) - s;
                        float saved = 0.0f;
#pragma unroll
                        for (int r = 0; r < p; r++) {
                            float den = rgt[r + 1] + lft[p - r];
                            float tmp = __fdividef(Nb[r], den);
                            Nb[r] = fmaf(rgt[r + 1], tmp, saved);
                            saved = lft[p - r] * tmp;
                        }
                        Nb[p] = saved;
                    }
                    const float* cq = Csh + q * NCTRL + j;   // coeff index (i-3)..i
                    float phi = Nb[0] * cq[0] + Nb[1] * cq[1] + Nb[2] * cq[2] + Nb[3] * cq[3];
                    res = fmaf(Msh[12 + q], phi, res);
                }
                out[myp] = res;
            }
        }
        tile = nxt;
        tpar ^= 1;
    }
}

extern "C" void kernel_launch(void* const* d_in, const int* in_sizes, int n_in,
                              void* d_out, int out_size) {
    const float* emb         = (const float*)d_in[0];
    const float* W           = (const float*)d_in[1];
    const float* b_inner     = (const float*)d_in[2];
    const float* inner_scale = (const float*)d_in[3];
    const float* coeffs      = (const float*)d_in[4];
    const float* a           = (const float*)d_in[5];
    const float* b_out       = (const float*)d_in[6];
    float* out = (float*)d_out;

    int npts   = out_size;                    // (N_POINTS, 1) float32
    int ntiles = (npts + TILE - 1) / TILE;
    int blocks = ntiles < GRIDMAX ? ntiles : GRIDMAX;

    // Reset the work-stealing counter (memset node: graph-capturable).
    void* ctr_ptr = nullptr;
    cudaGetSymbolAddress(&ctr_ptr, g_ctr);
    cudaMemsetAsync(ctr_ptr, 0, sizeof(int));

    cudaFuncSetAttribute(kan_bspline_kernel,
                         cudaFuncAttributeMaxDynamicSharedMemorySize, SMEM_BYTES);
    kan_bspline_kernel<<<blocks, BLOCK, SMEM_BYTES>>>(
        emb, W, b_inner, inner_scale, coeffs, a, b_out, out,
        npts, ntiles, blocks);
}